// round 1
// baseline (speedup 1.0000x reference)
#include <cuda_runtime.h>

#define BATCH  32
#define SMAX   222
#define S1     197
#define DMODEL 768
#define NLAYER 12
#define NHEAD  12
#define HDIM   64
#define MLPD   3072
#define POOL   10
#define SEL    5
#define PLEN   5
#define NCLS   100

// ---------------- scratch (static device allocations; harness-legal) ----------------
__device__ float g_x   [BATCH * SMAX * DMODEL];
__device__ float g_x0  [BATCH * S1   * DMODEL];
__device__ float g_h   [BATCH * SMAX * DMODEL];
__device__ float g_qkv [BATCH * SMAX * 3 * DMODEL];
__device__ float g_o   [BATCH * SMAX * DMODEL];
__device__ float g_mlp [BATCH * SMAX * MLPD];
__device__ float g_feat[BATCH * DMODEL];
__device__ float g_score[BATCH * POOL];
__device__ float g_lognorm[POOL];
__device__ float g_logwn[POOL];
__device__ int   g_topk[BATCH * SEL];

// ---------------- reductions (blockDim == 256 assumed) ----------------
__device__ __forceinline__ float block_sum256(float v, float* red) {
    int lane = threadIdx.x & 31, wid = threadIdx.x >> 5;
    #pragma unroll
    for (int o = 16; o; o >>= 1) v += __shfl_xor_sync(0xffffffffu, v, o);
    if (lane == 0) red[wid] = v;
    __syncthreads();
    float r = (lane < 8) ? red[lane] : 0.f;
    #pragma unroll
    for (int o = 4; o; o >>= 1) r += __shfl_xor_sync(0xffffffffu, r, o);
    r = __shfl_sync(0xffffffffu, r, 0);
    __syncthreads();
    return r;
}

__device__ __forceinline__ float block_max256(float v, float* red) {
    int lane = threadIdx.x & 31, wid = threadIdx.x >> 5;
    #pragma unroll
    for (int o = 16; o; o >>= 1) v = fmaxf(v, __shfl_xor_sync(0xffffffffu, v, o));
    if (lane == 0) red[wid] = v;
    __syncthreads();
    float r = (lane < 8) ? red[lane] : -1e30f;
    #pragma unroll
    for (int o = 4; o; o >>= 1) r = fmaxf(r, __shfl_xor_sync(0xffffffffu, r, o));
    r = __shfl_sync(0xffffffffu, r, 0);
    __syncthreads();
    return r;
}

// ---------------- tiled SGEMM: C[M,N] = A[M,K] @ W[K,N] + bias, epilogues ----------------
// mode 0 = store, 1 = exact GELU then store, 2 = add into C (residual)
#define BM 128
#define BN 64
#define BK 16

__global__ void __launch_bounds__(256) sgemm_kernel(
    const float* __restrict__ A, const float* __restrict__ W,
    const float* __restrict__ bias, float* __restrict__ C,
    int M, int N, int K, int mode)
{
    __shared__ float As[BK][BM];
    __shared__ float Ws[BK][BN];
    int tid = threadIdx.x;
    int tx = tid & 15, ty = tid >> 4;
    int row0 = blockIdx.y * BM;
    int col0 = blockIdx.x * BN;

    float acc[8][4];
    #pragma unroll
    for (int r = 0; r < 8; r++)
        #pragma unroll
        for (int c = 0; c < 4; c++) acc[r][c] = 0.f;

    for (int k0 = 0; k0 < K; k0 += BK) {
        #pragma unroll
        for (int i = 0; i < 8; i++) {
            int idx = tid + i * 256;       // 0..2047
            int m = idx >> 4;
            int kk = idx & 15;
            int gm = row0 + m;
            As[kk][m] = (gm < M) ? A[(size_t)gm * K + k0 + kk] : 0.f;
        }
        #pragma unroll
        for (int i = 0; i < 4; i++) {
            int idx = tid + i * 256;       // 0..1023
            int kk = idx >> 6;
            int n = idx & 63;
            Ws[kk][n] = W[(size_t)(k0 + kk) * N + col0 + n];
        }
        __syncthreads();
        #pragma unroll
        for (int kk = 0; kk < BK; kk++) {
            float a[8], w[4];
            #pragma unroll
            for (int r = 0; r < 8; r++) a[r] = As[kk][ty * 8 + r];
            #pragma unroll
            for (int c = 0; c < 4; c++) w[c] = Ws[kk][tx * 4 + c];
            #pragma unroll
            for (int r = 0; r < 8; r++)
                #pragma unroll
                for (int c = 0; c < 4; c++) acc[r][c] += a[r] * w[c];
        }
        __syncthreads();
    }

    int mbase = row0 + ty * 8;
    int nbase = col0 + tx * 4;
    #pragma unroll
    for (int r = 0; r < 8; r++) {
        int gm = mbase + r;
        if (gm >= M) continue;
        #pragma unroll
        for (int c = 0; c < 4; c++) {
            int gn = nbase + c;
            float v = acc[r][c] + bias[gn];
            if (mode == 1) v = 0.5f * v * (1.0f + erff(v * 0.70710678118654752f));
            size_t off = (size_t)gm * N + gn;
            if (mode == 2) C[off] += v;
            else C[off] = v;
        }
    }
}

// ---------------- LayerNorm over 768 (= 3*256) ----------------
__global__ void ln_kernel(const float* __restrict__ in, float* __restrict__ out,
                          const float* __restrict__ w, const float* __restrict__ b,
                          long long in_stride, long long out_stride)
{
    __shared__ float red[8];
    const float* x = in + (long long)blockIdx.x * in_stride;
    float* y = out + (long long)blockIdx.x * out_stride;
    int t = threadIdx.x;
    float v0 = x[t], v1 = x[t + 256], v2 = x[t + 512];
    float mean = block_sum256(v0 + v1 + v2, red) * (1.f / 768.f);
    float d0 = v0 - mean, d1 = v1 - mean, d2 = v2 - mean;
    float var = block_sum256(d0 * d0 + d1 * d1 + d2 * d2, red) * (1.f / 768.f);
    float rstd = rsqrtf(var + 1e-6f);
    y[t]       = d0 * rstd * w[t]       + b[t];
    y[t + 256] = d1 * rstd * w[t + 256] + b[t + 256];
    y[t + 512] = d2 * rstd * w[t + 512] + b[t + 512];
}

// ---------------- attention: one block per (q, head, batch) ----------------
__global__ void attn_kernel(const float* __restrict__ qkv, float* __restrict__ o, int S)
{
    int qi = blockIdx.x, h = blockIdx.y, b = blockIdx.z;
    __shared__ float qv[HDIM];
    __shared__ float pr[256];
    __shared__ float red[8];
    __shared__ float opart[4][HDIM];
    int tid = threadIdx.x;
    const float* base = qkv + (size_t)b * S * (3 * DMODEL);

    if (tid < HDIM) qv[tid] = base[(size_t)qi * (3 * DMODEL) + h * HDIM + tid];
    __syncthreads();

    float sc = -1e30f;
    if (tid < S) {
        const float* kp = base + (size_t)tid * (3 * DMODEL) + DMODEL + h * HDIM;
        float d = 0.f;
        #pragma unroll
        for (int i = 0; i < HDIM; i++) d += qv[i] * kp[i];
        sc = d * 0.125f;   // 64^-0.5
    }
    float mx = block_max256(sc, red);
    float e = (tid < S) ? expf(sc - mx) : 0.f;
    float sum = block_sum256(e, red);
    pr[tid] = e / sum;
    __syncthreads();

    int kg = tid >> 6, d = tid & 63;
    const float* vb = base + 2 * DMODEL + h * HDIM + d;
    float accv = 0.f;
    for (int k = kg; k < S; k += 4) accv += pr[k] * vb[(size_t)k * (3 * DMODEL)];
    opart[kg][d] = accv;
    __syncthreads();
    if (tid < HDIM) {
        float r = opart[0][tid] + opart[1][tid] + opart[2][tid] + opart[3][tid];
        o[((size_t)(b * S + qi)) * DMODEL + h * HDIM + tid] = r;
    }
}

// ---------------- patchify + embedding ----------------
__global__ void patchify_kernel(const float* __restrict__ in)
{
    size_t i = (size_t)blockIdx.x * 256 + threadIdx.x;
    if (i >= (size_t)BATCH * 196 * DMODEL) return;
    int v = (int)(i % DMODEL);
    size_t t = i / DMODEL;
    int p = (int)(t % 196);
    int b = (int)(t / 196);
    int c = v >> 8;                // / 256
    int py = (v & 255) >> 4;
    int px = v & 15;
    int gy = p / 14, gx = p % 14;
    g_mlp[i] = in[(((size_t)b * 3 + c) * 224 + gy * 16 + py) * 224 + gx * 16 + px];
}

__global__ void embed_kernel(const float* __restrict__ cls, const float* __restrict__ pos)
{
    size_t i = (size_t)blockIdx.x * 256 + threadIdx.x;
    if (i >= (size_t)BATCH * S1 * DMODEL) return;
    int d = (int)(i % DMODEL);
    size_t t = i / DMODEL;
    int s = (int)(t % S1);
    int b = (int)(t / S1);
    float v;
    if (s == 0) v = cls[d] + pos[d];
    else        v = g_o[((size_t)b * 196 + (s - 1)) * DMODEL + d] + pos[(size_t)s * DMODEL + d];
    g_x[i] = v;
    g_x0[i] = v;
}

// ---------------- routing ----------------
__global__ void pool_stats_kernel(const float* __restrict__ var)
{
    __shared__ float red[8];
    int p = blockIdx.x;
    const float* v = var + (size_t)p * DMODEL * DMODEL;
    float s = 0.f;
    for (int i = threadIdx.x; i < DMODEL * DMODEL; i += 256) { float t = v[i]; s += t * t; }
    float tot = block_sum256(s, red);
    if (threadIdx.x == 0) g_lognorm[p] = 0.25f * logf(tot);  // 0.5*log(sqrt(ss))
}

__global__ void logwn_kernel(const float* __restrict__ freq)
{
    float m = freq[0];
    for (int i = 1; i < POOL; i++) m = fmaxf(m, freq[i]);
    float w[POOL]; float ss = 0.f;
    for (int i = 0; i < POOL; i++) { w[i] = m - freq[i]; ss += w[i] * w[i]; }
    float nz = fmaxf(sqrtf(ss), 1e-12f);
    for (int i = 0; i < POOL; i++) g_logwn[i] = logf(fmaxf(w[i] / nz, 1e-30f));
}

__global__ void quad_kernel(const float* __restrict__ keys, const float* __restrict__ inv_var)
{
    __shared__ float diff[DMODEL];
    __shared__ float red[8];
    int b = blockIdx.x, p = blockIdx.y;
    for (int i = threadIdx.x; i < DMODEL; i += 256)
        diff[i] = g_feat[b * DMODEL + i] - keys[p * DMODEL + i];
    __syncthreads();
    const float* M = inv_var + (size_t)p * DMODEL * DMODEL;
    float acc = 0.f;
    for (int d = threadIdx.x; d < DMODEL; d += 256) {
        const float* row = M + (size_t)d * DMODEL;
        float t = 0.f;
        for (int e = 0; e < DMODEL; e++) t += row[e] * diff[e];
        acc += diff[d] * t;
    }
    float quad = block_sum256(acc, red);
    if (threadIdx.x == 0)
        g_score[b * POOL + p] = -0.5f * quad + g_lognorm[p] + g_logwn[p];
}

__global__ void topk_kernel()
{
    int b = threadIdx.x;
    if (b >= BATCH) return;
    float s[POOL]; bool used[POOL];
    for (int p = 0; p < POOL; p++) { s[p] = g_score[b * POOL + p]; used[p] = false; }
    for (int i = 0; i < SEL; i++) {
        int best = 0; float bv = 3.0e38f;
        for (int p = 0; p < POOL; p++)
            if (!used[p] && s[p] < bv) { bv = s[p]; best = p; }   // strict < : lowest index on tie
        used[best] = true;
        g_topk[b * SEL + i] = best;
    }
}

__global__ void build_sx_kernel(const float* __restrict__ prompts, const float* __restrict__ pos)
{
    size_t i = (size_t)blockIdx.x * 256 + threadIdx.x;
    if (i >= (size_t)BATCH * SMAX * DMODEL) return;
    int d = (int)(i % DMODEL);
    size_t t = i / DMODEL;
    int s = (int)(t % SMAX);
    int b = (int)(t / SMAX);
    float v;
    if (s == 0) {
        v = g_x0[(size_t)b * S1 * DMODEL + d];
    } else if (s <= SEL * PLEN) {
        int idx = s - 1;
        int pi = idx / PLEN, j = idx % PLEN;
        int pool = g_topk[b * SEL + pi];
        v = prompts[((size_t)pool * PLEN + j) * DMODEL + d] + pos[d];
    } else {
        v = g_x0[((size_t)b * S1 + (s - SEL * PLEN)) * DMODEL + d];
    }
    g_x[i] = v;
}

// ---------------- epilogue ----------------
__global__ void feat_kernel()
{
    int i = blockIdx.x * 256 + threadIdx.x;
    if (i >= BATCH * DMODEL) return;
    int b = i / DMODEL, d = i % DMODEL;
    float s = 0.f;
    for (int t = 1; t <= SEL * PLEN; t++)
        s += g_h[((size_t)b * SMAX + t) * DMODEL + d];
    g_feat[i] = s * (1.f / (SEL * PLEN));
}

__global__ void head_kernel(const float* __restrict__ hw, const float* __restrict__ hb,
                            float* __restrict__ out)
{
    int i = blockIdx.x * 256 + threadIdx.x;
    if (i >= BATCH * NCLS) return;
    int b = i / NCLS, n = i % NCLS;
    float acc = hb[n];
    for (int k = 0; k < DMODEL; k++) acc += g_feat[b * DMODEL + k] * hw[k * NCLS + n];
    out[i] = acc;
}

// ---------------- host orchestration ----------------
static void run_vit(int S, int M,
    const float* ln1w, const float* ln1b, const float* qkvw, const float* qkvb,
    const float* pw, const float* pb, const float* ln2w, const float* ln2b,
    const float* f1w, const float* f1b, const float* f2w, const float* f2b,
    float* px, float* ph, float* pqkv, float* po, float* pmlp)
{
    int gy = (M + BM - 1) / BM;
    for (int l = 0; l < NLAYER; l++) {
        ln_kernel<<<M, 256>>>(px, ph, ln1w + (size_t)l * DMODEL, ln1b + (size_t)l * DMODEL, DMODEL, DMODEL);
        sgemm_kernel<<<dim3(3 * DMODEL / BN, gy), 256>>>(ph, qkvw + (size_t)l * DMODEL * 3 * DMODEL,
                                                          qkvb + (size_t)l * 3 * DMODEL, pqkv, M, 3 * DMODEL, DMODEL, 0);
        attn_kernel<<<dim3(S, NHEAD, BATCH), 256>>>(pqkv, po, S);
        sgemm_kernel<<<dim3(DMODEL / BN, gy), 256>>>(po, pw + (size_t)l * DMODEL * DMODEL,
                                                      pb + (size_t)l * DMODEL, px, M, DMODEL, DMODEL, 2);
        ln_kernel<<<M, 256>>>(px, ph, ln2w + (size_t)l * DMODEL, ln2b + (size_t)l * DMODEL, DMODEL, DMODEL);
        sgemm_kernel<<<dim3(MLPD / BN, gy), 256>>>(ph, f1w + (size_t)l * DMODEL * MLPD,
                                                    f1b + (size_t)l * MLPD, pmlp, M, MLPD, DMODEL, 1);
        sgemm_kernel<<<dim3(DMODEL / BN, gy), 256>>>(pmlp, f2w + (size_t)l * MLPD * DMODEL,
                                                      f2b + (size_t)l * DMODEL, px, M, DMODEL, MLPD, 2);
    }
}

extern "C" void kernel_launch(void* const* d_in, const int* in_sizes, int n_in,
                              void* d_out, int out_size)
{
    const float* inputs    = (const float*)d_in[0];
    const float* patch_w   = (const float*)d_in[1];
    const float* patch_b   = (const float*)d_in[2];
    const float* cls_token = (const float*)d_in[3];
    const float* pos_embed = (const float*)d_in[4];
    const float* ln1_w = (const float*)d_in[5];
    const float* ln1_b = (const float*)d_in[6];
    const float* qkv_w = (const float*)d_in[7];
    const float* qkv_b = (const float*)d_in[8];
    const float* proj_w = (const float*)d_in[9];
    const float* proj_b = (const float*)d_in[10];
    const float* ln2_w = (const float*)d_in[11];
    const float* ln2_b = (const float*)d_in[12];
    const float* fc1_w = (const float*)d_in[13];
    const float* fc1_b = (const float*)d_in[14];
    const float* fc2_w = (const float*)d_in[15];
    const float* fc2_b = (const float*)d_in[16];
    const float* norm_w = (const float*)d_in[17];
    const float* norm_b = (const float*)d_in[18];
    const float* head_w = (const float*)d_in[19];
    const float* head_b = (const float*)d_in[20];
    const float* key_pool = (const float*)d_in[21];
    const float* frequency = (const float*)d_in[22];
    const float* prompts = (const float*)d_in[23];
    const float* variance = (const float*)d_in[24];
    const float* inv_variance = (const float*)d_in[25];

    float *px, *ph, *pqkv, *po, *pmlp, *pfeat;
    cudaGetSymbolAddress((void**)&px,   g_x);
    cudaGetSymbolAddress((void**)&ph,   g_h);
    cudaGetSymbolAddress((void**)&pqkv, g_qkv);
    cudaGetSymbolAddress((void**)&po,   g_o);
    cudaGetSymbolAddress((void**)&pmlp, g_mlp);
    cudaGetSymbolAddress((void**)&pfeat, g_feat);

    // 1) patch embed
    patchify_kernel<<<(BATCH * 196 * DMODEL + 255) / 256, 256>>>(inputs);
    sgemm_kernel<<<dim3(DMODEL / BN, (BATCH * 196 + BM - 1) / BM), 256>>>(
        pmlp, patch_w, patch_b, po, BATCH * 196, DMODEL, DMODEL, 0);
    embed_kernel<<<(BATCH * S1 * DMODEL + 255) / 256, 256>>>(cls_token, pos_embed);

    // 2) first ViT pass (S=197)
    run_vit(S1, BATCH * S1, ln1_w, ln1_b, qkv_w, qkv_b, proj_w, proj_b,
            ln2_w, ln2_b, fc1_w, fc1_b, fc2_w, fc2_b, px, ph, pqkv, po, pmlp);

    // 3) routing: LN on CLS token only -> g_feat, then Mahalanobis scores -> topk
    ln_kernel<<<BATCH, 256>>>(px, pfeat, norm_w, norm_b, (long long)S1 * DMODEL, DMODEL);
    pool_stats_kernel<<<POOL, 256>>>(variance);
    logwn_kernel<<<1, 1>>>(frequency);
    quad_kernel<<<dim3(BATCH, POOL), 256>>>(key_pool, inv_variance);
    topk_kernel<<<1, 32>>>();

    // 4) splice prompts into original embedding (S=222)
    build_sx_kernel<<<(BATCH * SMAX * DMODEL + 255) / 256, 256>>>(prompts, pos_embed);

    // 5) second ViT pass (S=222)
    run_vit(SMAX, BATCH * SMAX, ln1_w, ln1_b, qkv_w, qkv_b, proj_w, proj_b,
            ln2_w, ln2_b, fc1_w, fc1_b, fc2_w, fc2_b, px, ph, pqkv, po, pmlp);

    // 6) final LN, mean over prompt tokens, head
    ln_kernel<<<BATCH * SMAX, 256>>>(px, ph, norm_w, norm_b, DMODEL, DMODEL);
    feat_kernel<<<(BATCH * DMODEL + 255) / 256, 256>>>();
    head_kernel<<<(BATCH * NCLS + 255) / 256, 256>>>(head_w, head_b, (float*)d_out);
}